// round 1
// baseline (speedup 1.0000x reference)
#include <cuda_runtime.h>
#include <cuda_bf16.h>
#include <math.h>

// Problem constants (fixed shapes per reference)
#define NN 100000
#define EE 1600000
#define HH 4
#define CC 16
#define HC 64
#define IN_DIM 128

// -------- scratch (device globals; allocation-free at runtime) --------
static __device__ float4 g_xp4[NN * 16];      // xp [N,64] as float4x16
static __device__ float4 g_as4[NN];           // a_src [N,4]
static __device__ float4 g_ad4[NN];           // a_dst [N,4]
static __device__ uint4  g_m4[NN];            // segment max (ordered-uint encoding)
static __device__ float4 g_den4[NN];          // segment sum of exp
static __device__ float4 g_e4[EE];            // per-edge logits -> exp values

// ---------------- helpers ----------------
__device__ __forceinline__ unsigned ford(float f) {
    unsigned b = __float_as_uint(f);
    return (b & 0x80000000u) ? ~b : (b | 0x80000000u);
}
__device__ __forceinline__ float fdec(unsigned u) {
    return (u & 0x80000000u) ? __uint_as_float(u & 0x7fffffffu)
                             : __uint_as_float(~u);
}
__device__ __forceinline__ float lrelu(float v) {
    return v >= 0.f ? v : 0.2f * v;
}
__device__ __forceinline__ void red_add_v4(float* addr, float a, float b, float c, float d) {
    asm volatile("red.global.add.v4.f32 [%0], {%1, %2, %3, %4};"
                 :: "l"(addr), "f"(a), "f"(b), "f"(c), "f"(d) : "memory");
}

// ---------------- kernels ----------------

// init: out[i]=bias[i%64]; m=-inf(encoded); denom=0
__global__ void init_kernel(float* __restrict__ out, const float* __restrict__ bias, int n) {
    int i = blockIdx.x * blockDim.x + threadIdx.x;
    if (i < n * HC) out[i] = bias[i & 63];
    if (i < n * HH) {
        ((unsigned*)g_m4)[i] = 0x007FFFFFu;   // ford(-inf)
        ((float*)g_den4)[i]  = 0.f;
    }
}

// GEMM: xp = x @ W, fused a_src/a_dst epilogue.
// 256 threads/block = 8 warps, 4 rows per warp. W transposed in smem (pad 129).
__global__ __launch_bounds__(256) void gemm_kernel(
    const float* __restrict__ x, const float* __restrict__ W,
    const float* __restrict__ att_src, const float* __restrict__ att_dst, int n)
{
    __shared__ float sWt[HC * 129];   // [c][k], padded
    __shared__ float sAs[HC], sAd[HC];
    int tid = threadIdx.x;
    for (int i = tid; i < HC * IN_DIM; i += blockDim.x) {
        int c = i >> 7, k = i & 127;
        sWt[c * 129 + k] = W[k * HC + c];
    }
    if (tid < HC) { sAs[tid] = att_src[tid]; sAd[tid] = att_dst[tid]; }
    __syncthreads();

    int warp = tid >> 5, lane = tid & 31;
    const int RPW = 4;
    int r0 = (blockIdx.x * 8 + warp) * RPW;

    float xr[RPW][4];
    float acc[RPW][2];
#pragma unroll
    for (int r = 0; r < RPW; r++) {
        acc[r][0] = 0.f; acc[r][1] = 0.f;
        int row = r0 + r;
        if (row < n) {
#pragma unroll
            for (int j = 0; j < 4; j++) xr[r][j] = x[(size_t)row * IN_DIM + j * 32 + lane];
        } else {
#pragma unroll
            for (int j = 0; j < 4; j++) xr[r][j] = 0.f;
        }
    }

#pragma unroll
    for (int j = 0; j < 4; j++) {
#pragma unroll 8
        for (int kk = 0; kk < 32; kk++) {
            int k = j * 32 + kk;
            float w0 = sWt[lane * 129 + k];
            float w1 = sWt[(lane + 32) * 129 + k];
#pragma unroll
            for (int r = 0; r < RPW; r++) {
                float xk = __shfl_sync(0xffffffffu, xr[r][j], kk);
                acc[r][0] = fmaf(xk, w0, acc[r][0]);
                acc[r][1] = fmaf(xk, w1, acc[r][1]);
            }
        }
    }

    float as0 = sAs[lane], as1 = sAs[lane + 32];
    float ad0 = sAd[lane], ad1 = sAd[lane + 32];
#pragma unroll
    for (int r = 0; r < RPW; r++) {
        int row = r0 + r;
        if (row >= n) continue;
        float* xp = (float*)g_xp4 + (size_t)row * HC;
        xp[lane]      = acc[r][0];
        xp[lane + 32] = acc[r][1];
        // attention reductions within 16-lane groups
        float ps0 = acc[r][0] * as0, ps1 = acc[r][1] * as1;
        float pd0 = acc[r][0] * ad0, pd1 = acc[r][1] * ad1;
#pragma unroll
        for (int o = 8; o >= 1; o >>= 1) {
            ps0 += __shfl_xor_sync(0xffffffffu, ps0, o);
            ps1 += __shfl_xor_sync(0xffffffffu, ps1, o);
            pd0 += __shfl_xor_sync(0xffffffffu, pd0, o);
            pd1 += __shfl_xor_sync(0xffffffffu, pd1, o);
        }
        if ((lane & 15) == 0) {
            int g = lane >> 4;  // 0 or 1
            float* as_ = (float*)&g_as4[row];
            float* ad_ = (float*)&g_ad4[row];
            as_[g]     = ps0;  as_[2 + g] = ps1;
            ad_[g]     = pd0;  ad_[2 + g] = pd1;
        }
    }
}

// pass A: logits + leaky relu + segment max
__global__ __launch_bounds__(256) void edge_logits_kernel(const int* __restrict__ ei, int e) {
    int t = blockIdx.x * blockDim.x + threadIdx.x;
    if (t >= e) return;
    int s = ei[t], d = ei[e + t];
    float4 a = g_as4[s];
    float4 b = g_ad4[d];
    float4 l;
    l.x = lrelu(a.x + b.x); l.y = lrelu(a.y + b.y);
    l.z = lrelu(a.z + b.z); l.w = lrelu(a.w + b.w);
    g_e4[t] = l;
    unsigned* mb = (unsigned*)&g_m4[d];
    atomicMax(mb + 0, ford(l.x));
    atomicMax(mb + 1, ford(l.y));
    atomicMax(mb + 2, ford(l.z));
    atomicMax(mb + 3, ford(l.w));
}

// pass B: e = exp(logit - m[dst]); denom += e
__global__ __launch_bounds__(256) void edge_exp_kernel(const int* __restrict__ ei, int e) {
    int t = blockIdx.x * blockDim.x + threadIdx.x;
    if (t >= e) return;
    int d = ei[e + t];
    float4 l = g_e4[t];
    uint4 mu = g_m4[d];
    float4 ev;
    ev.x = expf(l.x - fdec(mu.x));
    ev.y = expf(l.y - fdec(mu.y));
    ev.z = expf(l.z - fdec(mu.z));
    ev.w = expf(l.w - fdec(mu.w));
    g_e4[t] = ev;
    red_add_v4((float*)&g_den4[d], ev.x, ev.y, ev.z, ev.w);
}

// pass C: alpha = e/(denom+eps); out[dst] += xp[src]*alpha ; write alpha
// 16 threads per edge, each handles one float4 of the 64-wide message.
__global__ __launch_bounds__(256) void edge_scatter_kernel(
    const int* __restrict__ ei, int e, float* __restrict__ out, float* __restrict__ alpha_out)
{
    int t = blockIdx.x * blockDim.x + threadIdx.x;
    if (t >= e * 16) return;
    int ed = t >> 4, q = t & 15, h = q >> 2;
    int s = ei[ed], d = ei[e + ed];
    const float* den = (const float*)&g_den4[d];
    const float* ev  = (const float*)&g_e4[ed];
    float al = ev[h] / (den[h] + 1e-16f);
    float4 xv = g_xp4[(size_t)s * 16 + q];
    red_add_v4(out + (size_t)d * HC + q * 4, xv.x * al, xv.y * al, xv.z * al, xv.w * al);
    if (q == 0 && alpha_out != nullptr) {
        float4 e4 = g_e4[ed];
        float4 dn = g_den4[d];
        float4 a4;
        a4.x = e4.x / (dn.x + 1e-16f);
        a4.y = e4.y / (dn.y + 1e-16f);
        a4.z = e4.z / (dn.z + 1e-16f);
        a4.w = e4.w / (dn.w + 1e-16f);
        ((float4*)alpha_out)[ed] = a4;
    }
}

// copy edge_index as float into output region
__global__ __launch_bounds__(256) void copy_ei_kernel(const int* __restrict__ ei,
                                                      float* __restrict__ dst, int n2e) {
    int i = blockIdx.x * blockDim.x + threadIdx.x;
    if (i < n2e) dst[i] = (float)ei[i];
}

extern "C" void kernel_launch(void* const* d_in, const int* in_sizes, int n_in,
                              void* d_out, int out_size) {
    const float* x       = (const float*)d_in[0];
    const float* W       = (const float*)d_in[1];
    const float* att_src = (const float*)d_in[2];
    const float* att_dst = (const float*)d_in[3];
    const float* bias    = (const float*)d_in[4];
    const int*   ei      = (const int*)d_in[5];
    float* out = (float*)d_out;

    int n = in_sizes[0] / IN_DIM;   // 100000
    int e = in_sizes[5] / 2;        // 1600000
    long nhc = (long)n * HC;

    init_kernel<<<(n * HC + 511) / 512, 512>>>(out, bias, n);

    int gemm_blocks = (n + 8 * 4 - 1) / (8 * 4);
    gemm_kernel<<<gemm_blocks, 256>>>(x, W, att_src, att_dst, n);

    edge_logits_kernel<<<(e + 255) / 256, 256>>>(ei, e);
    edge_exp_kernel<<<(e + 255) / 256, 256>>>(ei, e);

    float* ei_out = nullptr;
    float* alpha_out = nullptr;
    if ((long)out_size >= nhc + 2L * e)          ei_out    = out + nhc;
    if ((long)out_size >= nhc + 2L * e + 4L * e) alpha_out = out + nhc + 2L * e;

    edge_scatter_kernel<<<(e * 16 + 255) / 256, 256>>>(ei, e, out, alpha_out);

    if (ei_out)
        copy_ei_kernel<<<(2 * e + 255) / 256, 256>>>(ei, ei_out, 2 * e);
}

// round 2
// speedup vs baseline: 1.7067x; 1.7067x over previous
#include <cuda_runtime.h>
#include <math.h>

#define NN 100000
#define EE 1600000
#define HC 64
#define IN_DIM 128

// ---------------- scratch (device globals, allocation-free) ----------------
static __device__ float  g_xp[(size_t)NN * HC];   // xp [N,64]
static __device__ float4 g_as4[NN];               // a_src [N,4]
static __device__ float4 g_ad4[NN];               // a_dst [N,4]
static __device__ float4 g_m4[NN];                // per-node segment max
static __device__ float4 g_rcp4[NN];              // per-node 1/(denom+eps)
static __device__ int    g_cnt[NN];               // degree histogram
static __device__ int    g_fill[NN];              // fill cursors
static __device__ int    g_rowptr[NN + 1];        // CSR row pointers
static __device__ int    g_bsum[512];             // scan partials
static __device__ int    g_boff[512];             // scan offsets
static __device__ int    g_csr_src[EE];           // CSR src ids

__device__ __forceinline__ float lrelu(float v) { return v >= 0.f ? v : 0.2f * v; }

// ---------------- init: zero histogram + cursors ----------------
__global__ void init_kernel(int n) {
    int i = blockIdx.x * blockDim.x + threadIdx.x;
    if (i < n) { g_cnt[i] = 0; g_fill[i] = 0; }
}

// ---------------- GEMM: xp = x @ W  (64x64 tile, 4x4 per thread) ----------------
__global__ __launch_bounds__(256) void gemm_kernel(
    const float* __restrict__ x, const float* __restrict__ W, int n)
{
    __shared__ float xs[64 * 64];   // [k(64)][row(64)]
    __shared__ float ws[64 * 64];   // [k(64)][col(64)]
    int tid = threadIdx.x;
    int tx = tid & 15, ty = tid >> 4;
    int r0 = blockIdx.x * 64;

    float acc[4][4];
#pragma unroll
    for (int a = 0; a < 4; a++)
#pragma unroll
        for (int b = 0; b < 4; b++) acc[a][b] = 0.f;

    for (int kh = 0; kh < 2; kh++) {
        // stage x tile transposed: xs[k][row]
#pragma unroll
        for (int q = 0; q < 4; q++) {
            int idx = tid + q * 256;          // 0..1023
            int kq  = idx >> 6;               // float4 index in k (0..15)
            int row = idx & 63;
            float4 v = make_float4(0.f, 0.f, 0.f, 0.f);
            int grow = r0 + row;
            if (grow < n)
                v = *(const float4*)(x + (size_t)grow * IN_DIM + kh * 64 + kq * 4);
            xs[(kq * 4 + 0) * 64 + row] = v.x;
            xs[(kq * 4 + 1) * 64 + row] = v.y;
            xs[(kq * 4 + 2) * 64 + row] = v.z;
            xs[(kq * 4 + 3) * 64 + row] = v.w;
        }
        // stage W half: ws[k][col]
#pragma unroll
        for (int q = 0; q < 4; q++) {
            int idx = tid + q * 256;          // 0..1023
            int k  = idx >> 4;                // 0..63
            int c4 = idx & 15;
            *(float4*)(ws + k * 64 + c4 * 4) =
                *(const float4*)(W + (size_t)(kh * 64 + k) * HC + c4 * 4);
        }
        __syncthreads();
#pragma unroll 8
        for (int k = 0; k < 64; k++) {
            float4 xa = *(const float4*)(xs + k * 64 + ty * 4);
            float4 wb = *(const float4*)(ws + k * 64 + tx * 4);
            acc[0][0] = fmaf(xa.x, wb.x, acc[0][0]);
            acc[0][1] = fmaf(xa.x, wb.y, acc[0][1]);
            acc[0][2] = fmaf(xa.x, wb.z, acc[0][2]);
            acc[0][3] = fmaf(xa.x, wb.w, acc[0][3]);
            acc[1][0] = fmaf(xa.y, wb.x, acc[1][0]);
            acc[1][1] = fmaf(xa.y, wb.y, acc[1][1]);
            acc[1][2] = fmaf(xa.y, wb.z, acc[1][2]);
            acc[1][3] = fmaf(xa.y, wb.w, acc[1][3]);
            acc[2][0] = fmaf(xa.z, wb.x, acc[2][0]);
            acc[2][1] = fmaf(xa.z, wb.y, acc[2][1]);
            acc[2][2] = fmaf(xa.z, wb.z, acc[2][2]);
            acc[2][3] = fmaf(xa.z, wb.w, acc[2][3]);
            acc[3][0] = fmaf(xa.w, wb.x, acc[3][0]);
            acc[3][1] = fmaf(xa.w, wb.y, acc[3][1]);
            acc[3][2] = fmaf(xa.w, wb.z, acc[3][2]);
            acc[3][3] = fmaf(xa.w, wb.w, acc[3][3]);
        }
        __syncthreads();
    }
#pragma unroll
    for (int r = 0; r < 4; r++) {
        int row = r0 + ty * 4 + r;
        if (row < n) {
            float4 o = make_float4(acc[r][0], acc[r][1], acc[r][2], acc[r][3]);
            *(float4*)(g_xp + (size_t)row * HC + tx * 4) = o;
        }
    }
}

// ---------------- per-node attention halves from xp ----------------
__global__ __launch_bounds__(256) void attn_kernel(
    const float* __restrict__ att_src, const float* __restrict__ att_dst, int n)
{
    int w = (blockIdx.x * blockDim.x + threadIdx.x) >> 5;
    int lane = threadIdx.x & 31;
    if (w >= n) return;
    float v0 = g_xp[(size_t)w * HC + lane];
    float v1 = g_xp[(size_t)w * HC + 32 + lane];
    float ps0 = v0 * att_src[lane],      ps1 = v1 * att_src[lane + 32];
    float pd0 = v0 * att_dst[lane],      pd1 = v1 * att_dst[lane + 32];
#pragma unroll
    for (int o = 8; o >= 1; o >>= 1) {
        ps0 += __shfl_xor_sync(0xffffffffu, ps0, o);
        ps1 += __shfl_xor_sync(0xffffffffu, ps1, o);
        pd0 += __shfl_xor_sync(0xffffffffu, pd0, o);
        pd1 += __shfl_xor_sync(0xffffffffu, pd1, o);
    }
    if ((lane & 15) == 0) {
        int g = lane >> 4;
        float* as_ = (float*)&g_as4[w];
        float* ad_ = (float*)&g_ad4[w];
        as_[g] = ps0;  as_[2 + g] = ps1;
        ad_[g] = pd0;  ad_[2 + g] = pd1;
    }
}

// ---------------- CSR build ----------------
__global__ void hist_kernel(const int* __restrict__ ei, int e) {
    int t = blockIdx.x * blockDim.x + threadIdx.x;
    if (t < e) atomicAdd(&g_cnt[ei[e + t]], 1);
}

__global__ void scan1_kernel(int n) {
    __shared__ int sd[512];
    int t = threadIdx.x, i = blockIdx.x * 512 + t;
    int v = (i < n) ? g_cnt[i] : 0;
    sd[t] = v; __syncthreads();
    for (int off = 1; off < 512; off <<= 1) {
        int x = (t >= off) ? sd[t - off] : 0;
        __syncthreads();
        sd[t] += x;
        __syncthreads();
    }
    if (i < n) g_rowptr[i + 1] = sd[t];
    if (t == 511) g_bsum[blockIdx.x] = sd[511];
}

__global__ void scan2_kernel(int nb) {
    __shared__ int sd[512];
    int t = threadIdx.x;
    int v = (t < nb) ? g_bsum[t] : 0;
    sd[t] = v; __syncthreads();
    for (int off = 1; off < 512; off <<= 1) {
        int x = (t >= off) ? sd[t - off] : 0;
        __syncthreads();
        sd[t] += x;
        __syncthreads();
    }
    g_boff[t] = sd[t] - v;   // exclusive
}

__global__ void scan3_kernel(int n) {
    int i = blockIdx.x * 512 + threadIdx.x;
    if (i < n) g_rowptr[i + 1] += g_boff[blockIdx.x];
    if (i == 0) g_rowptr[0] = 0;
}

__global__ void fill_kernel(const int* __restrict__ ei, int e) {
    int t = blockIdx.x * blockDim.x + threadIdx.x;
    if (t >= e) return;
    int s = ei[t], d = ei[e + t];
    int pos = atomicAdd(&g_fill[d], 1);
    g_csr_src[g_rowptr[d] + pos] = s;
}

// ---------------- fused softmax + aggregation: one warp per dst node ----------------
__global__ __launch_bounds__(256) void aggregate_kernel(
    const float* __restrict__ bias, float* __restrict__ out, int n)
{
    __shared__ float sE[8][32][4];
    int w = (blockIdx.x * 256 + threadIdx.x) >> 5;
    int lane = threadIdx.x & 31, wl = threadIdx.x >> 5;
    if (w >= n) return;                 // uniform per warp; only __syncwarp below

    int start = g_rowptr[w];
    int deg   = g_rowptr[w + 1] - start;
    float4 ad = g_ad4[w];

    // pass 1: segment max
    float4 m = make_float4(-INFINITY, -INFINITY, -INFINITY, -INFINITY);
    for (int base = 0; base < deg; base += 32) {
        int i = base + lane;
        if (i < deg) {
            float4 a = g_as4[g_csr_src[start + i]];
            m.x = fmaxf(m.x, lrelu(a.x + ad.x));
            m.y = fmaxf(m.y, lrelu(a.y + ad.y));
            m.z = fmaxf(m.z, lrelu(a.z + ad.z));
            m.w = fmaxf(m.w, lrelu(a.w + ad.w));
        }
    }
#pragma unroll
    for (int o = 16; o >= 1; o >>= 1) {
        m.x = fmaxf(m.x, __shfl_xor_sync(0xffffffffu, m.x, o));
        m.y = fmaxf(m.y, __shfl_xor_sync(0xffffffffu, m.y, o));
        m.z = fmaxf(m.z, __shfl_xor_sync(0xffffffffu, m.z, o));
        m.w = fmaxf(m.w, __shfl_xor_sync(0xffffffffu, m.w, o));
    }

    // pass 2: e = exp(l - m); denom partials; acc += e * xp[src]
    float4 ds = make_float4(0.f, 0.f, 0.f, 0.f);
    float acc0 = 0.f, acc1 = 0.f;
    int h0 = lane >> 4;      // head for col=lane; col=lane+32 is head h0+2

    for (int base = 0; base < deg; base += 32) {
        int i = base + lane;
        int s = 0;
        float4 ev = make_float4(0.f, 0.f, 0.f, 0.f);
        if (i < deg) {
            s = g_csr_src[start + i];
            float4 a = g_as4[s];
            ev.x = expf(lrelu(a.x + ad.x) - m.x);
            ev.y = expf(lrelu(a.y + ad.y) - m.y);
            ev.z = expf(lrelu(a.z + ad.z) - m.z);
            ev.w = expf(lrelu(a.w + ad.w) - m.w);
            ds.x += ev.x; ds.y += ev.y; ds.z += ev.z; ds.w += ev.w;
        }
        sE[wl][lane][0] = ev.x; sE[wl][lane][1] = ev.y;
        sE[wl][lane][2] = ev.z; sE[wl][lane][3] = ev.w;
        __syncwarp();
        int cnt = min(32, deg - base);
        const float* sEj = &sE[wl][0][0];
#pragma unroll 4
        for (int j = 0; j < cnt; j++) {
            int sj = __shfl_sync(0xffffffffu, s, j);
            float e0 = sEj[j * 4 + h0];
            float e1 = sEj[j * 4 + 2 + h0];
            const float* xp = g_xp + (size_t)sj * HC;
            acc0 = fmaf(__ldg(xp + lane),      e0, acc0);
            acc1 = fmaf(__ldg(xp + 32 + lane), e1, acc1);
        }
        __syncwarp();
    }
#pragma unroll
    for (int o = 16; o >= 1; o >>= 1) {
        ds.x += __shfl_xor_sync(0xffffffffu, ds.x, o);
        ds.y += __shfl_xor_sync(0xffffffffu, ds.y, o);
        ds.z += __shfl_xor_sync(0xffffffffu, ds.z, o);
        ds.w += __shfl_xor_sync(0xffffffffu, ds.w, o);
    }
    float4 r;
    r.x = 1.f / (ds.x + 1e-16f); r.y = 1.f / (ds.y + 1e-16f);
    r.z = 1.f / (ds.z + 1e-16f); r.w = 1.f / (ds.w + 1e-16f);
    if (lane == 0) { g_m4[w] = m; g_rcp4[w] = r; }

    float r0 = h0 ? r.y : r.x;
    float r1 = h0 ? r.w : r.z;
    out[(size_t)w * HC + lane]      = acc0 * r0 + bias[lane];
    out[(size_t)w * HC + 32 + lane] = acc1 * r1 + bias[lane + 32];
}

// ---------------- alpha in edge order (coalesced), from stored (m, rcp) ----------------
__global__ __launch_bounds__(256) void alpha_kernel(
    const int* __restrict__ ei, int e, float* __restrict__ alpha_out)
{
    int t = blockIdx.x * blockDim.x + threadIdx.x;
    if (t >= e) return;
    int s = ei[t], d = ei[e + t];
    float4 a = g_as4[s], b = g_ad4[d], m = g_m4[d], r = g_rcp4[d];
    float4 o;
    o.x = expf(lrelu(a.x + b.x) - m.x) * r.x;
    o.y = expf(lrelu(a.y + b.y) - m.y) * r.y;
    o.z = expf(lrelu(a.z + b.z) - m.z) * r.z;
    o.w = expf(lrelu(a.w + b.w) - m.w) * r.w;
    ((float4*)alpha_out)[t] = o;
}

__global__ __launch_bounds__(256) void copy_ei_kernel(const int* __restrict__ ei,
                                                      float* __restrict__ dst, int n2e) {
    int i = blockIdx.x * blockDim.x + threadIdx.x;
    if (i < n2e) dst[i] = (float)ei[i];
}

extern "C" void kernel_launch(void* const* d_in, const int* in_sizes, int n_in,
                              void* d_out, int out_size) {
    const float* x       = (const float*)d_in[0];
    const float* W       = (const float*)d_in[1];
    const float* att_src = (const float*)d_in[2];
    const float* att_dst = (const float*)d_in[3];
    const float* bias    = (const float*)d_in[4];
    const int*   ei      = (const int*)d_in[5];
    float* out = (float*)d_out;

    int n = in_sizes[0] / IN_DIM;   // 100000
    int e = in_sizes[5] / 2;        // 1600000
    long nhc = (long)n * HC;
    int nb = (n + 511) / 512;

    init_kernel<<<(n + 511) / 512, 512>>>(n);
    gemm_kernel<<<(n + 63) / 64, 256>>>(x, W, n);
    attn_kernel<<<(n * 32 + 255) / 256, 256>>>(att_src, att_dst, n);
    hist_kernel<<<(e + 255) / 256, 256>>>(ei, e);
    scan1_kernel<<<nb, 512>>>(n);
    scan2_kernel<<<1, 512>>>(nb);
    scan3_kernel<<<nb, 512>>>(n);
    fill_kernel<<<(e + 255) / 256, 256>>>(ei, e);
    aggregate_kernel<<<(n * 32 + 255) / 256, 256>>>(bias, out, n);

    float* ei_out = nullptr;
    float* alpha_out = nullptr;
    if ((long)out_size >= nhc + 2L * e)          ei_out    = out + nhc;
    if ((long)out_size >= nhc + 2L * e + 4L * e) alpha_out = out + nhc + 2L * e;

    if (alpha_out)
        alpha_kernel<<<(e + 255) / 256, 256>>>(ei, e, alpha_out);
    if (ei_out)
        copy_ei_kernel<<<(2 * e + 255) / 256, 256>>>(ei, ei_out, 2 * e);
}